// round 1
// baseline (speedup 1.0000x reference)
#include <cuda_runtime.h>
#include <math.h>

#define NN 50000
#define EE 1600000
#define TOT (EE + NN)     // edges + self loops
#define HC 128            // H*C
#define NEG_SLOPE 0.2f

// ---------------- scratch (__device__ globals; no allocation) ----------------
__device__ float g_x[NN * HC];          // projected features  [N,128]
__device__ float g_as[NN * 2];          // a_src terms [N,H]
__device__ float g_ad[NN * 2];          // a_dst terms [N,H]
__device__ int   g_counts[NN];
__device__ int   g_offsets[NN + 1];
__device__ int   g_cursor[NN];
__device__ int   g_ssrc[TOT];           // src ids sorted (grouped) by dst

// ---------------- 1) init counts to 1 (self loop) ----------------
__global__ void k_init_counts() {
    int i = blockIdx.x * blockDim.x + threadIdx.x;
    if (i < NN) g_counts[i] = 1;
}

// ---------------- 2) histogram of dst ----------------
__global__ void k_hist(const int* __restrict__ ei) {
    int e = blockIdx.x * blockDim.x + threadIdx.x;
    if (e < EE) atomicAdd(&g_counts[ei[EE + e]], 1);
}

// ---------------- 3) exclusive scan over 50000 counts (single block) --------
__global__ void k_scan() {
    __shared__ int warp_sums[32];
    __shared__ int s_carry;
    int tid = threadIdx.x, lane = tid & 31, wid = tid >> 5;
    if (tid == 0) s_carry = 0;
    __syncthreads();
    for (int base = 0; base < NN; base += 1024) {
        int i = base + tid;
        int v = (i < NN) ? g_counts[i] : 0;
        int x = v;
        #pragma unroll
        for (int d = 1; d < 32; d <<= 1) {
            int t = __shfl_up_sync(0xffffffffu, x, d);
            if (lane >= d) x += t;
        }
        if (lane == 31) warp_sums[wid] = x;
        __syncthreads();
        if (wid == 0) {
            int s = warp_sums[lane];
            #pragma unroll
            for (int d = 1; d < 32; d <<= 1) {
                int t = __shfl_up_sync(0xffffffffu, s, d);
                if (lane >= d) s += t;
            }
            warp_sums[lane] = s;
        }
        __syncthreads();
        int warp_off = (wid == 0) ? 0 : warp_sums[wid - 1];
        int excl = s_carry + warp_off + x - v;
        if (i < NN) { g_offsets[i] = excl; g_cursor[i] = excl; }
        int total = warp_sums[31];
        __syncthreads();
        if (tid == 0) s_carry += total;
        __syncthreads();
    }
    if (threadIdx.x == 0) g_offsets[NN] = s_carry;
}

// ---------------- 4) scatter edges (+ self loops) into CSR ----------------
__global__ void k_scatter(const int* __restrict__ ei) {
    int idx = blockIdx.x * blockDim.x + threadIdx.x;
    if (idx < EE) {
        int src = ei[idx];
        int dst = ei[EE + idx];
        int pos = atomicAdd(&g_cursor[dst], 1);
        g_ssrc[pos] = src;
    } else if (idx < TOT) {
        int n = idx - EE;
        int pos = atomicAdd(&g_cursor[n], 1);
        g_ssrc[pos] = n;
    }
}

// ---------------- 5) GEMM x = h_node @ W  (fp32 FMA, 32 rows/block) ---------
__global__ void k_gemm(const float* __restrict__ A, const float* __restrict__ W) {
    __shared__ float As[32 * 128];
    int tid = threadIdx.x;
    int j = tid & 127;      // output column
    int g = tid >> 7;       // row group (0/1) -> 16 rows each
    int row0 = blockIdx.x * 32;

    // load A tile [32][128] (guarded, zero pad)
    {
        float4* Asv = (float4*)As;
        const float4* Ag = (const float4*)(A + (size_t)row0 * 128);
        for (int i = tid; i < 32 * 32; i += 256) {
            int row = row0 + (i >> 5);
            float4 v;
            if (row < NN) v = Ag[i];
            else { v.x = v.y = v.z = v.w = 0.f; }
            Asv[i] = v;
        }
    }
    __syncthreads();

    float acc[16];
    #pragma unroll
    for (int r = 0; r < 16; r++) acc[r] = 0.f;

    for (int k = 0; k < 128; k++) {
        float wv = __ldg(W + k * 128 + j);
        #pragma unroll
        for (int r = 0; r < 16; r++)
            acc[r] += As[(g * 16 + r) * 128 + k] * wv;
    }

    #pragma unroll
    for (int r = 0; r < 16; r++) {
        int row = row0 + g * 16 + r;
        if (row < NN) g_x[(size_t)row * 128 + j] = acc[r];
    }
}

// ---------------- 6) per-node attention terms a_s, a_d ----------------
__global__ void k_attn_terms(const float* __restrict__ att_src,
                             const float* __restrict__ att_dst) {
    int w = (blockIdx.x * blockDim.x + threadIdx.x) >> 5;
    if (w >= NN) return;
    int lane = threadIdx.x & 31;
    float4 v = ((const float4*)g_x)[(size_t)w * 32 + lane];
    float4 s4 = ((const float4*)att_src)[lane];   // [H*C]=128 floats = 32 float4
    float4 d4 = ((const float4*)att_dst)[lane];
    float ps = v.x * s4.x + v.y * s4.y + v.z * s4.z + v.w * s4.w;
    float pd = v.x * d4.x + v.y * d4.y + v.z * d4.z + v.w * d4.w;
    // reduce within 16-lane groups (lanes 0-15: head0, 16-31: head1)
    #pragma unroll
    for (int d = 8; d >= 1; d >>= 1) {
        ps += __shfl_xor_sync(0xffffffffu, ps, d);
        pd += __shfl_xor_sync(0xffffffffu, pd, d);
    }
    if (lane == 0)  { g_as[2 * w + 0] = ps; g_ad[2 * w + 0] = pd; }
    if (lane == 16) { g_as[2 * w + 1] = ps; g_ad[2 * w + 1] = pd; }
}

// ---------------- 7) main: edge softmax + aggregate (warp per dst node) -----
__device__ __forceinline__ float leaky(float x) {
    return x > 0.f ? x : NEG_SLOPE * x;
}

__global__ void k_aggregate(const float* __restrict__ bias, float* __restrict__ out) {
    int w = (blockIdx.x * blockDim.x + threadIdx.x) >> 5;
    if (w >= NN) return;
    int lane = threadIdx.x & 31;
    int beg = g_offsets[w], end = g_offsets[w + 1];

    float ad0 = g_ad[2 * w], ad1 = g_ad[2 * w + 1];

    // pass 1: per-head max
    float m0 = -3.4e38f, m1 = -3.4e38f;
    for (int j = beg + lane; j < end; j += 32) {
        int s = g_ssrc[j];
        float e0 = leaky(g_as[2 * s + 0] + ad0);
        float e1 = leaky(g_as[2 * s + 1] + ad1);
        m0 = fmaxf(m0, e0); m1 = fmaxf(m1, e1);
    }
    #pragma unroll
    for (int d = 16; d >= 1; d >>= 1) {
        m0 = fmaxf(m0, __shfl_xor_sync(0xffffffffu, m0, d));
        m1 = fmaxf(m1, __shfl_xor_sync(0xffffffffu, m1, d));
    }

    // pass 2: denominators
    float den0 = 0.f, den1 = 0.f;
    for (int j = beg + lane; j < end; j += 32) {
        int s = g_ssrc[j];
        float e0 = leaky(g_as[2 * s + 0] + ad0);
        float e1 = leaky(g_as[2 * s + 1] + ad1);
        den0 += __expf ? expf(e0 - m0) : 0.f, den1 += expf(e1 - m1);
        // (note: plain expf used; first expr keeps fp32 expf path)
        den0 += 0.f;
    }
    // fix: recompute cleanly (avoid the conditional artifact above)
    den0 = 0.f; den1 = 0.f;
    for (int j = beg + lane; j < end; j += 32) {
        int s = g_ssrc[j];
        float e0 = leaky(g_as[2 * s + 0] + ad0);
        float e1 = leaky(g_as[2 * s + 1] + ad1);
        den0 += expf(e0 - m0);
        den1 += expf(e1 - m1);
    }
    #pragma unroll
    for (int d = 16; d >= 1; d >>= 1) {
        den0 += __shfl_xor_sync(0xffffffffu, den0, d);
        den1 += __shfl_xor_sync(0xffffffffu, den1, d);
    }
    float inv0 = 1.0f / den0;
    float inv1 = 1.0f / den1;

    // pass 3: accumulate alpha * x[src]; lane owns cols [lane*4, lane*4+4)
    int h = lane >> 4;                       // head for this lane's columns
    float adh  = h ? ad1 : ad0;
    float mh   = h ? m1  : m0;
    float invh = h ? inv1 : inv0;

    float4 acc = make_float4(0.f, 0.f, 0.f, 0.f);
    int s_cur = (beg < end) ? g_ssrc[beg] : 0;
    for (int j = beg; j < end; j++) {
        int s_next = (j + 1 < end) ? g_ssrc[j + 1] : 0;
        float as = g_as[2 * s_cur + h];
        float4 v = ((const float4*)g_x)[(size_t)s_cur * 32 + lane];
        float e = leaky(as + adh);
        float alpha = expf(e - mh) * invh;
        acc.x += alpha * v.x;
        acc.y += alpha * v.y;
        acc.z += alpha * v.z;
        acc.w += alpha * v.w;
        s_cur = s_next;
    }

    float4 b = ((const float4*)bias)[lane];
    acc.x += b.x; acc.y += b.y; acc.z += b.z; acc.w += b.w;
    acc.x = acc.x > 0.f ? acc.x : expm1f(acc.x);
    acc.y = acc.y > 0.f ? acc.y : expm1f(acc.y);
    acc.z = acc.z > 0.f ? acc.z : expm1f(acc.z);
    acc.w = acc.w > 0.f ? acc.w : expm1f(acc.w);
    ((float4*)out)[(size_t)w * 32 + lane] = acc;
}

// ---------------- launch ----------------
extern "C" void kernel_launch(void* const* d_in, const int* in_sizes, int n_in,
                              void* d_out, int out_size) {
    const float* h_node  = (const float*)d_in[0];
    const int*   ei      = (const int*)d_in[1];
    const float* W       = (const float*)d_in[2];
    const float* att_src = (const float*)d_in[3];
    const float* att_dst = (const float*)d_in[4];
    const float* bias    = (const float*)d_in[5];
    float* out = (float*)d_out;

    k_init_counts<<<(NN + 255) / 256, 256>>>();
    k_hist<<<(EE + 255) / 256, 256>>>(ei);
    k_scan<<<1, 1024>>>();
    k_scatter<<<(TOT + 255) / 256, 256>>>(ei);
    k_gemm<<<(NN + 31) / 32, 256>>>(h_node, W);
    k_attn_terms<<<(NN * 32 + 255) / 256, 256>>>(att_src, att_dst);
    k_aggregate<<<(NN * 32 + 255) / 256, 256>>>(bias, out);
}

// round 2
// speedup vs baseline: 1.2499x; 1.2499x over previous
#include <cuda_runtime.h>
#include <math.h>

#define NN 50000
#define EE 1600000
#define TOT (EE + NN)
#define HC 128
#define NEG_SLOPE 0.2f
#define NCHUNK 49   // ceil(50000/1024)

// ---------------- scratch ----------------
__device__ float g_x[NN * HC];
__device__ float g_as[NN * 2];
__device__ float g_ad[NN * 2];
__device__ int   g_counts[NN];
__device__ int   g_offsets[NN + 1];
__device__ int   g_cursor[NN];
__device__ int   g_ssrc[TOT];
__device__ int   g_bsum[NCHUNK];

// ---------------- 1) init counts to 1 (self loop) ----------------
__global__ void k_init_counts() {
    int i = blockIdx.x * blockDim.x + threadIdx.x;
    if (i < NN) g_counts[i] = 1;
}

// ---------------- 2) histogram of dst (int4 loads) ----------------
__global__ void k_hist(const int* __restrict__ ei) {
    int t = blockIdx.x * blockDim.x + threadIdx.x;
    if (t < EE / 4) {
        int4 d = ((const int4*)(ei + EE))[t];
        atomicAdd(&g_counts[d.x], 1);
        atomicAdd(&g_counts[d.y], 1);
        atomicAdd(&g_counts[d.z], 1);
        atomicAdd(&g_counts[d.w], 1);
    }
}

// ---------------- 3a) chunk sums ----------------
__global__ void k_chunksum() {
    __shared__ int ws[8];
    int b = blockIdx.x;
    int base = b * 1024;
    int sum = 0;
    for (int i = threadIdx.x; i < 1024; i += 256) {
        int idx = base + i;
        if (idx < NN) sum += g_counts[idx];
    }
    #pragma unroll
    for (int d = 16; d >= 1; d >>= 1) sum += __shfl_xor_sync(0xffffffffu, sum, d);
    int lane = threadIdx.x & 31, wid = threadIdx.x >> 5;
    if (lane == 0) ws[wid] = sum;
    __syncthreads();
    if (threadIdx.x == 0) {
        int s = 0;
        #pragma unroll
        for (int i = 0; i < 8; i++) s += ws[i];
        g_bsum[b] = s;
    }
}

// ---------------- 3b) per-chunk scan with chunk prefix ----------------
__global__ void k_scan2() {
    __shared__ int s_pref[64];
    __shared__ int s_total;
    __shared__ int warp_sums[32];
    int b = blockIdx.x;
    int tid = threadIdx.x, lane = tid & 31, wid = tid >> 5;

    // phase A: warp 0 computes exclusive prefix of all chunk sums
    if (wid == 0) {
        int v0 = (lane < NCHUNK) ? g_bsum[lane] : 0;
        int v1 = (32 + lane < NCHUNK) ? g_bsum[32 + lane] : 0;
        int x = v0;
        #pragma unroll
        for (int d = 1; d < 32; d <<= 1) {
            int t = __shfl_up_sync(0xffffffffu, x, d);
            if (lane >= d) x += t;
        }
        int tot0 = __shfl_sync(0xffffffffu, x, 31);
        int y = v1;
        #pragma unroll
        for (int d = 1; d < 32; d <<= 1) {
            int t = __shfl_up_sync(0xffffffffu, y, d);
            if (lane >= d) y += t;
        }
        s_pref[lane] = x - v0;                 // exclusive
        s_pref[32 + lane] = tot0 + y - v1;
        if (lane == 31) s_total = tot0 + y;
    }
    __syncthreads();
    int prev = s_pref[b];

    // phase B: local scan of this chunk's 1024 counts
    int i = b * 1024 + tid;
    int v = (i < NN) ? g_counts[i] : 0;
    int x = v;
    #pragma unroll
    for (int d = 1; d < 32; d <<= 1) {
        int t = __shfl_up_sync(0xffffffffu, x, d);
        if (lane >= d) x += t;
    }
    if (lane == 31) warp_sums[wid] = x;
    __syncthreads();
    if (wid == 0) {
        int s = warp_sums[lane];
        #pragma unroll
        for (int d = 1; d < 32; d <<= 1) {
            int t = __shfl_up_sync(0xffffffffu, s, d);
            if (lane >= d) s += t;
        }
        warp_sums[lane] = s;
    }
    __syncthreads();
    int excl = (wid ? warp_sums[wid - 1] : 0) + x - v;
    if (i < NN) {
        int off = prev + excl;
        g_offsets[i] = off;
        g_cursor[i] = off;
    }
    if (b == 0 && tid == 0) g_offsets[NN] = s_total;
}

// ---------------- 4) scatter edges (+ self loops) into CSR ----------------
__global__ void k_scatter(const int* __restrict__ ei) {
    int t = blockIdx.x * blockDim.x + threadIdx.x;
    const int EQ = EE / 4;
    if (t < EQ) {
        int4 s = ((const int4*)ei)[t];
        int4 d = ((const int4*)(ei + EE))[t];
        int p;
        p = atomicAdd(&g_cursor[d.x], 1); g_ssrc[p] = s.x;
        p = atomicAdd(&g_cursor[d.y], 1); g_ssrc[p] = s.y;
        p = atomicAdd(&g_cursor[d.z], 1); g_ssrc[p] = s.z;
        p = atomicAdd(&g_cursor[d.w], 1); g_ssrc[p] = s.w;
    } else if (t - EQ < NN) {
        int n = t - EQ;
        int p = atomicAdd(&g_cursor[n], 1);
        g_ssrc[p] = n;
    }
}

// ---------------- 5) GEMM x = h_node @ W  (fp32x2 packed FMA) ----------------
// block = 64 rows x 128 cols, 256 threads; thread tile = 8 rows x 4 cols.
// As is stored transposed [k][row] with pitch 66 so LDS.64 yields packed row pairs.
__global__ void k_gemm(const float* __restrict__ A, const float* __restrict__ W) {
    __shared__ __align__(16) float As[128 * 66];
    int tid = threadIdx.x;
    int tc = tid & 31;         // thread col group (4 cols)
    int tr = tid >> 5;         // thread row group (8 rows)
    int row0 = blockIdx.x * 64;

    // load A tile transposed
    const float4* Ag = (const float4*)A;
    for (int i = tid; i < 64 * 32; i += 256) {
        int r = i >> 5, kq = i & 31;
        int row = row0 + r;
        float4 v = (row < NN) ? Ag[(size_t)row * 32 + kq] : make_float4(0.f, 0.f, 0.f, 0.f);
        As[(4 * kq + 0) * 66 + r] = v.x;
        As[(4 * kq + 1) * 66 + r] = v.y;
        As[(4 * kq + 2) * 66 + r] = v.z;
        As[(4 * kq + 3) * 66 + r] = v.w;
    }
    __syncthreads();

    unsigned long long acc[4][4];
    #pragma unroll
    for (int r = 0; r < 4; r++)
        #pragma unroll
        for (int c = 0; c < 4; c++) acc[r][c] = 0ull;

    const float4* Wg = (const float4*)W;
    int rbase = tr * 8;

    #pragma unroll 4
    for (int k = 0; k < 128; k++) {
        float4 w4 = __ldg(&Wg[k * 32 + tc]);
        unsigned long long ww[4];
        asm("mov.b64 %0, {%1, %1};" : "=l"(ww[0]) : "f"(w4.x));
        asm("mov.b64 %0, {%1, %1};" : "=l"(ww[1]) : "f"(w4.y));
        asm("mov.b64 %0, {%1, %1};" : "=l"(ww[2]) : "f"(w4.z));
        asm("mov.b64 %0, {%1, %1};" : "=l"(ww[3]) : "f"(w4.w));
        unsigned long long ap[4];
        #pragma unroll
        for (int r = 0; r < 4; r++) {
            float2 a2 = *(const float2*)&As[k * 66 + rbase + 2 * r];
            asm("mov.b64 %0, {%1, %2};" : "=l"(ap[r]) : "f"(a2.x), "f"(a2.y));
        }
        #pragma unroll
        for (int r = 0; r < 4; r++)
            #pragma unroll
            for (int c = 0; c < 4; c++)
                asm("fma.rn.f32x2 %0, %1, %2, %0;" : "+l"(acc[r][c]) : "l"(ap[r]), "l"(ww[c]));
    }

    // epilogue: unpack pairs, store
    #pragma unroll
    for (int r = 0; r < 4; r++) {
        float lo[4], hi[4];
        #pragma unroll
        for (int c = 0; c < 4; c++)
            asm("mov.b64 {%0, %1}, %2;" : "=f"(lo[c]), "=f"(hi[c]) : "l"(acc[r][c]));
        int rowA = row0 + rbase + 2 * r;
        int rowB = rowA + 1;
        if (rowA < NN)
            ((float4*)g_x)[(size_t)rowA * 32 + tc] = make_float4(lo[0], lo[1], lo[2], lo[3]);
        if (rowB < NN)
            ((float4*)g_x)[(size_t)rowB * 32 + tc] = make_float4(hi[0], hi[1], hi[2], hi[3]);
    }
}

// ---------------- 6) per-node attention terms ----------------
__global__ void k_attn_terms(const float* __restrict__ att_src,
                             const float* __restrict__ att_dst) {
    int w = (blockIdx.x * blockDim.x + threadIdx.x) >> 5;
    if (w >= NN) return;
    int lane = threadIdx.x & 31;
    float4 v = ((const float4*)g_x)[(size_t)w * 32 + lane];
    float4 s4 = ((const float4*)att_src)[lane];
    float4 d4 = ((const float4*)att_dst)[lane];
    float ps = v.x * s4.x + v.y * s4.y + v.z * s4.z + v.w * s4.w;
    float pd = v.x * d4.x + v.y * d4.y + v.z * d4.z + v.w * d4.w;
    #pragma unroll
    for (int d = 8; d >= 1; d >>= 1) {
        ps += __shfl_xor_sync(0xffffffffu, ps, d);
        pd += __shfl_xor_sync(0xffffffffu, pd, d);
    }
    if (lane == 0)  { g_as[2 * w + 0] = ps; g_ad[2 * w + 0] = pd; }
    if (lane == 16) { g_as[2 * w + 1] = ps; g_ad[2 * w + 1] = pd; }
}

// ---------------- 7) single-pass edge softmax + aggregate ----------------
__device__ __forceinline__ float leaky(float x) {
    return x > 0.f ? x : NEG_SLOPE * x;
}

__global__ void k_aggregate(const float* __restrict__ bias, float* __restrict__ out) {
    int w = (blockIdx.x * blockDim.x + threadIdx.x) >> 5;
    if (w >= NN) return;
    int lane = threadIdx.x & 31;
    int h = lane >> 4;
    int beg = g_offsets[w], end = g_offsets[w + 1];

    float adh = g_ad[2 * w + h];
    const float4* x4 = (const float4*)g_x;

    float den = 0.f;
    float4 acc = make_float4(0.f, 0.f, 0.f, 0.f);

    // software pipeline: s two ahead, (as, v) one ahead
    int sA = 0, sB = 0;
    float asA = 0.f;
    float4 vA = make_float4(0.f, 0.f, 0.f, 0.f);
    if (beg < end) {
        sA = g_ssrc[beg];
        asA = g_as[2 * sA + h];
        vA = x4[(size_t)sA * 32 + lane];
    }
    if (beg + 1 < end) sB = g_ssrc[beg + 1];

    for (int j = beg; j < end; ++j) {
        int sC = (j + 2 < end) ? g_ssrc[j + 2] : 0;
        float asB = 0.f;
        float4 vB = vA;
        if (j + 1 < end) {
            asB = g_as[2 * sB + h];
            vB = x4[(size_t)sB * 32 + lane];
        }
        float p = __expf(leaky(asA + adh));
        den += p;
        acc.x += p * vA.x;
        acc.y += p * vA.y;
        acc.z += p * vA.z;
        acc.w += p * vA.w;
        sA = sB; sB = sC; asA = asB; vA = vB;
    }

    float inv = 1.0f / den;
    float4 b = ((const float4*)bias)[lane];
    acc.x = acc.x * inv + b.x;
    acc.y = acc.y * inv + b.y;
    acc.z = acc.z * inv + b.z;
    acc.w = acc.w * inv + b.w;
    acc.x = acc.x > 0.f ? acc.x : expm1f(acc.x);
    acc.y = acc.y > 0.f ? acc.y : expm1f(acc.y);
    acc.z = acc.z > 0.f ? acc.z : expm1f(acc.z);
    acc.w = acc.w > 0.f ? acc.w : expm1f(acc.w);
    ((float4*)out)[(size_t)w * 32 + lane] = acc;
}

// ---------------- launch ----------------
extern "C" void kernel_launch(void* const* d_in, const int* in_sizes, int n_in,
                              void* d_out, int out_size) {
    const float* h_node  = (const float*)d_in[0];
    const int*   ei      = (const int*)d_in[1];
    const float* W       = (const float*)d_in[2];
    const float* att_src = (const float*)d_in[3];
    const float* att_dst = (const float*)d_in[4];
    const float* bias    = (const float*)d_in[5];
    float* out = (float*)d_out;

    k_init_counts<<<(NN + 255) / 256, 256>>>();
    k_hist<<<(EE / 4 + 255) / 256, 256>>>(ei);
    k_chunksum<<<NCHUNK, 256>>>();
    k_scan2<<<NCHUNK, 1024>>>();
    k_scatter<<<(EE / 4 + NN + 255) / 256, 256>>>(ei);
    k_gemm<<<(NN + 63) / 64, 256>>>(h_node, W);
    k_attn_terms<<<(NN * 32 + 255) / 256, 256>>>(att_src, att_dst);
    k_aggregate<<<(NN * 32 + 255) / 256, 256>>>(bias, out);
}

// round 3
// speedup vs baseline: 1.4786x; 1.1830x over previous
#include <cuda_runtime.h>
#include <math.h>

#define NN 50000
#define EE 1600000
#define TOT (EE + NN)
#define HC 128
#define NEG_SLOPE 0.2f
#define NCHUNK 49        // ceil(50000/1024)
#define G_GEMM 782       // ceil(50000/64)

// ---------------- scratch ----------------
__device__ float g_x[NN * HC];
__device__ float g_as[NN * 2];
__device__ float g_ad[NN * 2];
__device__ int   g_counts[NN];
__device__ int   g_offsets[NN + 1];
__device__ int   g_cursor[NN];
__device__ int   g_ssrc[TOT];
__device__ int   g_bsum[NCHUNK];

// ---------------- 1) init counts to 1 (self loop), vectorized --------------
__global__ void k_init_counts() {
    int i = blockIdx.x * blockDim.x + threadIdx.x;
    if (i < NN / 4) ((int4*)g_counts)[i] = make_int4(1, 1, 1, 1);
}

// ---------------- 2) fused GEMM (+attn terms) and histogram ----------------
// blocks [0, G_GEMM): GEMM x = h_node @ W, fp32x2 packed FMA, attn epilogue
// blocks [G_GEMM, ..): histogram of dst
__global__ void k_gemm_hist(const float* __restrict__ A, const float* __restrict__ W,
                            const float* __restrict__ att_src,
                            const float* __restrict__ att_dst,
                            const int* __restrict__ ei) {
    __shared__ __align__(16) float As[128 * 66];

    if (blockIdx.x >= G_GEMM) {
        // -------- histogram branch --------
        int t = (blockIdx.x - G_GEMM) * blockDim.x + threadIdx.x;
        if (t < EE / 4) {
            int4 d = ((const int4*)(ei + EE))[t];
            atomicAdd(&g_counts[d.x], 1);
            atomicAdd(&g_counts[d.y], 1);
            atomicAdd(&g_counts[d.z], 1);
            atomicAdd(&g_counts[d.w], 1);
        }
        return;
    }

    // -------- GEMM branch --------
    int tid = threadIdx.x;
    int tc = tid & 31;         // col group (4 cols)
    int tr = tid >> 5;         // row group (8 rows) == warp id
    int row0 = blockIdx.x * 64;

    const float4* Ag = (const float4*)A;
    for (int i = tid; i < 64 * 32; i += 256) {
        int r = i >> 5, kq = i & 31;
        int row = row0 + r;
        float4 v = (row < NN) ? Ag[(size_t)row * 32 + kq] : make_float4(0.f, 0.f, 0.f, 0.f);
        As[(4 * kq + 0) * 66 + r] = v.x;
        As[(4 * kq + 1) * 66 + r] = v.y;
        As[(4 * kq + 2) * 66 + r] = v.z;
        As[(4 * kq + 3) * 66 + r] = v.w;
    }
    __syncthreads();

    unsigned long long acc[4][4];
    #pragma unroll
    for (int r = 0; r < 4; r++)
        #pragma unroll
        for (int c = 0; c < 4; c++) acc[r][c] = 0ull;

    const float4* Wg = (const float4*)W;
    int rbase = tr * 8;

    #pragma unroll 4
    for (int k = 0; k < 128; k++) {
        float4 w4 = __ldg(&Wg[k * 32 + tc]);
        unsigned long long ww[4];
        asm("mov.b64 %0, {%1, %1};" : "=l"(ww[0]) : "f"(w4.x));
        asm("mov.b64 %0, {%1, %1};" : "=l"(ww[1]) : "f"(w4.y));
        asm("mov.b64 %0, {%1, %1};" : "=l"(ww[2]) : "f"(w4.z));
        asm("mov.b64 %0, {%1, %1};" : "=l"(ww[3]) : "f"(w4.w));
        unsigned long long ap[4];
        #pragma unroll
        for (int r = 0; r < 4; r++) {
            float2 a2 = *(const float2*)&As[k * 66 + rbase + 2 * r];
            asm("mov.b64 %0, {%1, %2};" : "=l"(ap[r]) : "f"(a2.x), "f"(a2.y));
        }
        #pragma unroll
        for (int r = 0; r < 4; r++)
            #pragma unroll
            for (int c = 0; c < 4; c++)
                asm("fma.rn.f32x2 %0, %1, %2, %0;" : "+l"(acc[r][c]) : "l"(ap[r]), "l"(ww[c]));
    }

    // epilogue: unpack, store x, and compute attention terms in-register
    float4 sA4 = ((const float4*)att_src)[tc];
    float4 dA4 = ((const float4*)att_dst)[tc];

    #pragma unroll
    for (int r = 0; r < 4; r++) {
        float lo[4], hi[4];
        #pragma unroll
        for (int c = 0; c < 4; c++)
            asm("mov.b64 {%0, %1}, %2;" : "=f"(lo[c]), "=f"(hi[c]) : "l"(acc[r][c]));
        int rowA = row0 + rbase + 2 * r;
        int rowB = rowA + 1;
        if (rowA < NN)
            ((float4*)g_x)[(size_t)rowA * 32 + tc] = make_float4(lo[0], lo[1], lo[2], lo[3]);
        if (rowB < NN)
            ((float4*)g_x)[(size_t)rowB * 32 + tc] = make_float4(hi[0], hi[1], hi[2], hi[3]);

        float psA = lo[0] * sA4.x + lo[1] * sA4.y + lo[2] * sA4.z + lo[3] * sA4.w;
        float pdA = lo[0] * dA4.x + lo[1] * dA4.y + lo[2] * dA4.z + lo[3] * dA4.w;
        float psB = hi[0] * sA4.x + hi[1] * sA4.y + hi[2] * sA4.z + hi[3] * sA4.w;
        float pdB = hi[0] * dA4.x + hi[1] * dA4.y + hi[2] * dA4.z + hi[3] * dA4.w;
        #pragma unroll
        for (int d = 8; d >= 1; d >>= 1) {
            psA += __shfl_xor_sync(0xffffffffu, psA, d);
            pdA += __shfl_xor_sync(0xffffffffu, pdA, d);
            psB += __shfl_xor_sync(0xffffffffu, psB, d);
            pdB += __shfl_xor_sync(0xffffffffu, pdB, d);
        }
        if ((tc == 0 || tc == 16)) {
            int hh = tc >> 4;
            if (rowA < NN) { g_as[2 * rowA + hh] = psA; g_ad[2 * rowA + hh] = pdA; }
            if (rowB < NN) { g_as[2 * rowB + hh] = psB; g_ad[2 * rowB + hh] = pdB; }
        }
    }
}

// ---------------- 3a) chunk sums ----------------
__global__ void k_chunksum() {
    __shared__ int ws[8];
    int b = blockIdx.x;
    int base = b * 1024;
    int sum = 0;
    for (int i = threadIdx.x; i < 1024; i += 256) {
        int idx = base + i;
        if (idx < NN) sum += g_counts[idx];
    }
    #pragma unroll
    for (int d = 16; d >= 1; d >>= 1) sum += __shfl_xor_sync(0xffffffffu, sum, d);
    int lane = threadIdx.x & 31, wid = threadIdx.x >> 5;
    if (lane == 0) ws[wid] = sum;
    __syncthreads();
    if (threadIdx.x == 0) {
        int s = 0;
        #pragma unroll
        for (int i = 0; i < 8; i++) s += ws[i];
        g_bsum[b] = s;
    }
}

// ---------------- 3b) per-chunk scan with chunk prefix ----------------
__global__ void k_scan2() {
    __shared__ int s_pref[64];
    __shared__ int s_total;
    __shared__ int warp_sums[32];
    int b = blockIdx.x;
    int tid = threadIdx.x, lane = tid & 31, wid = tid >> 5;

    if (wid == 0) {
        int v0 = (lane < NCHUNK) ? g_bsum[lane] : 0;
        int v1 = (32 + lane < NCHUNK) ? g_bsum[32 + lane] : 0;
        int x = v0;
        #pragma unroll
        for (int d = 1; d < 32; d <<= 1) {
            int t = __shfl_up_sync(0xffffffffu, x, d);
            if (lane >= d) x += t;
        }
        int tot0 = __shfl_sync(0xffffffffu, x, 31);
        int y = v1;
        #pragma unroll
        for (int d = 1; d < 32; d <<= 1) {
            int t = __shfl_up_sync(0xffffffffu, y, d);
            if (lane >= d) y += t;
        }
        s_pref[lane] = x - v0;
        s_pref[32 + lane] = tot0 + y - v1;
        if (lane == 31) s_total = tot0 + y;
    }
    __syncthreads();
    int prev = s_pref[b];

    int i = b * 1024 + tid;
    int v = (i < NN) ? g_counts[i] : 0;
    int x = v;
    #pragma unroll
    for (int d = 1; d < 32; d <<= 1) {
        int t = __shfl_up_sync(0xffffffffu, x, d);
        if (lane >= d) x += t;
    }
    if (lane == 31) warp_sums[wid] = x;
    __syncthreads();
    if (wid == 0) {
        int s = warp_sums[lane];
        #pragma unroll
        for (int d = 1; d < 32; d <<= 1) {
            int t = __shfl_up_sync(0xffffffffu, s, d);
            if (lane >= d) s += t;
        }
        warp_sums[lane] = s;
    }
    __syncthreads();
    int excl = (wid ? warp_sums[wid - 1] : 0) + x - v;
    if (i < NN) {
        int off = prev + excl;
        g_offsets[i] = off;
        g_cursor[i] = off;
    }
    if (b == 0 && tid == 0) g_offsets[NN] = s_total;
}

// ---------------- 4) scatter edges (+ self loops) into CSR ----------------
__global__ void k_scatter(const int* __restrict__ ei) {
    int t = blockIdx.x * blockDim.x + threadIdx.x;
    const int EQ = EE / 4;
    if (t < EQ) {
        int4 s = ((const int4*)ei)[t];
        int4 d = ((const int4*)(ei + EE))[t];
        int p;
        p = atomicAdd(&g_cursor[d.x], 1); g_ssrc[p] = s.x;
        p = atomicAdd(&g_cursor[d.y], 1); g_ssrc[p] = s.y;
        p = atomicAdd(&g_cursor[d.z], 1); g_ssrc[p] = s.z;
        p = atomicAdd(&g_cursor[d.w], 1); g_ssrc[p] = s.w;
    } else if (t - EQ < NN) {
        int n = t - EQ;
        int p = atomicAdd(&g_cursor[n], 1);
        g_ssrc[p] = n;
    }
}

// ---------------- 5) single-pass edge softmax + aggregate ----------------
__device__ __forceinline__ float leaky(float x) {
    return x > 0.f ? x : NEG_SLOPE * x;
}

__global__ void k_aggregate(const float* __restrict__ bias, float* __restrict__ out) {
    int w = (blockIdx.x * blockDim.x + threadIdx.x) >> 5;
    if (w >= NN) return;
    int lane = threadIdx.x & 31;
    int h = lane >> 4;
    int beg = g_offsets[w], end = g_offsets[w + 1];

    float adh = g_ad[2 * w + h];
    const float4* x4 = (const float4*)g_x;

    float den = 0.f;
    float4 acc = make_float4(0.f, 0.f, 0.f, 0.f);

    for (int base = beg; base < end; base += 32) {
        int nb = min(32, end - base);
        int idx = 0;
        float2 as2 = make_float2(0.f, 0.f);
        if (lane < nb) {
            idx = g_ssrc[base + lane];
            as2 = *(const float2*)&g_as[2 * idx];
        }
        if (nb == 32) {
            #pragma unroll 8
            for (int jj = 0; jj < 32; jj++) {
                int s = __shfl_sync(0xffffffffu, idx, jj);
                float a0 = __shfl_sync(0xffffffffu, as2.x, jj);
                float a1 = __shfl_sync(0xffffffffu, as2.y, jj);
                float p = __expf(leaky((h ? a1 : a0) + adh));
                float4 v = x4[(size_t)s * 32 + lane];
                den += p;
                acc.x += p * v.x;
                acc.y += p * v.y;
                acc.z += p * v.z;
                acc.w += p * v.w;
            }
        } else {
            for (int jj = 0; jj < nb; jj++) {
                int s = __shfl_sync(0xffffffffu, idx, jj);
                float a0 = __shfl_sync(0xffffffffu, as2.x, jj);
                float a1 = __shfl_sync(0xffffffffu, as2.y, jj);
                float p = __expf(leaky((h ? a1 : a0) + adh));
                float4 v = x4[(size_t)s * 32 + lane];
                den += p;
                acc.x += p * v.x;
                acc.y += p * v.y;
                acc.z += p * v.z;
                acc.w += p * v.w;
            }
        }
    }

    float inv = 1.0f / den;
    float4 b = ((const float4*)bias)[lane];
    acc.x = acc.x * inv + b.x;
    acc.y = acc.y * inv + b.y;
    acc.z = acc.z * inv + b.z;
    acc.w = acc.w * inv + b.w;
    acc.x = acc.x > 0.f ? acc.x : expm1f(acc.x);
    acc.y = acc.y > 0.f ? acc.y : expm1f(acc.y);
    acc.z = acc.z > 0.f ? acc.z : expm1f(acc.z);
    acc.w = acc.w > 0.f ? acc.w : expm1f(acc.w);
    ((float4*)out)[(size_t)w * 32 + lane] = acc;
}

// ---------------- launch ----------------
extern "C" void kernel_launch(void* const* d_in, const int* in_sizes, int n_in,
                              void* d_out, int out_size) {
    const float* h_node  = (const float*)d_in[0];
    const int*   ei      = (const int*)d_in[1];
    const float* W       = (const float*)d_in[2];
    const float* att_src = (const float*)d_in[3];
    const float* att_dst = (const float*)d_in[4];
    const float* bias    = (const float*)d_in[5];
    float* out = (float*)d_out;

    k_init_counts<<<(NN / 4 + 255) / 256, 256>>>();
    int hist_blocks = (EE / 4 + 255) / 256;
    k_gemm_hist<<<G_GEMM + hist_blocks, 256>>>(h_node, W, att_src, att_dst, ei);
    k_chunksum<<<NCHUNK, 256>>>();
    k_scan2<<<NCHUNK, 1024>>>();
    k_scatter<<<(EE / 4 + NN + 255) / 256, 256>>>(ei);
    k_aggregate<<<(NN * 32 + 255) / 256, 256>>>(bias, out);
}

// round 4
// speedup vs baseline: 1.5744x; 1.0648x over previous
#include <cuda_runtime.h>
#include <cuda_fp16.h>
#include <math.h>

#define NN 50000
#define EE 1600000
#define TOT (EE + NN)
#define HC 128
#define NEG_SLOPE 0.2f
#define NCHUNK 49        // ceil(50000/1024)
#define G_GEMM 782       // ceil(50000/64)

// ---------------- scratch ----------------
__device__ float  g_x[NN * HC];        // fp32 projected features (for attn epilogue correctness path)
__device__ __half g_xh[NN * HC];       // fp16 copy for the gather
__device__ float  g_as[NN * 2];
__device__ float  g_ad[NN * 2];
__device__ int    g_counts[NN];
__device__ int    g_offsets[NN + 1];
__device__ int    g_cursor[NN];
__device__ int    g_ssrc[TOT];
__device__ int    g_bsum[NCHUNK];

// ---------------- 1) init counts to 1 (self loop), vectorized --------------
__global__ void k_init_counts() {
    int i = blockIdx.x * blockDim.x + threadIdx.x;
    if (i < NN / 4) ((int4*)g_counts)[i] = make_int4(1, 1, 1, 1);
}

// ---------------- 2) histogram of dst (int4 loads) ----------------
__global__ void k_hist(const int* __restrict__ ei) {
    int t = blockIdx.x * blockDim.x + threadIdx.x;
    if (t < EE / 4) {
        int4 d = ((const int4*)(ei + EE))[t];
        atomicAdd(&g_counts[d.x], 1);
        atomicAdd(&g_counts[d.y], 1);
        atomicAdd(&g_counts[d.z], 1);
        atomicAdd(&g_counts[d.w], 1);
    }
}

// ---------------- 3a) chunk sums ----------------
__global__ void k_chunksum() {
    __shared__ int ws[8];
    int b = blockIdx.x;
    int base = b * 1024;
    int sum = 0;
    for (int i = threadIdx.x; i < 1024; i += 256) {
        int idx = base + i;
        if (idx < NN) sum += g_counts[idx];
    }
    #pragma unroll
    for (int d = 16; d >= 1; d >>= 1) sum += __shfl_xor_sync(0xffffffffu, sum, d);
    int lane = threadIdx.x & 31, wid = threadIdx.x >> 5;
    if (lane == 0) ws[wid] = sum;
    __syncthreads();
    if (threadIdx.x == 0) {
        int s = 0;
        #pragma unroll
        for (int i = 0; i < 8; i++) s += ws[i];
        g_bsum[b] = s;
    }
}

// ---------------- 3b) per-chunk scan with chunk prefix ----------------
__global__ void k_scan2() {
    __shared__ int s_pref[64];
    __shared__ int s_total;
    __shared__ int warp_sums[32];
    int b = blockIdx.x;
    int tid = threadIdx.x, lane = tid & 31, wid = tid >> 5;

    if (wid == 0) {
        int v0 = (lane < NCHUNK) ? g_bsum[lane] : 0;
        int v1 = (32 + lane < NCHUNK) ? g_bsum[32 + lane] : 0;
        int x = v0;
        #pragma unroll
        for (int d = 1; d < 32; d <<= 1) {
            int t = __shfl_up_sync(0xffffffffu, x, d);
            if (lane >= d) x += t;
        }
        int tot0 = __shfl_sync(0xffffffffu, x, 31);
        int y = v1;
        #pragma unroll
        for (int d = 1; d < 32; d <<= 1) {
            int t = __shfl_up_sync(0xffffffffu, y, d);
            if (lane >= d) y += t;
        }
        s_pref[lane] = x - v0;
        s_pref[32 + lane] = tot0 + y - v1;
        if (lane == 31) s_total = tot0 + y;
    }
    __syncthreads();
    int prev = s_pref[b];

    int i = b * 1024 + tid;
    int v = (i < NN) ? g_counts[i] : 0;
    int x = v;
    #pragma unroll
    for (int d = 1; d < 32; d <<= 1) {
        int t = __shfl_up_sync(0xffffffffu, x, d);
        if (lane >= d) x += t;
    }
    if (lane == 31) warp_sums[wid] = x;
    __syncthreads();
    if (wid == 0) {
        int s = warp_sums[lane];
        #pragma unroll
        for (int d = 1; d < 32; d <<= 1) {
            int t = __shfl_up_sync(0xffffffffu, s, d);
            if (lane >= d) s += t;
        }
        warp_sums[lane] = s;
    }
    __syncthreads();
    int excl = (wid ? warp_sums[wid - 1] : 0) + x - v;
    if (i < NN) {
        int off = prev + excl;
        g_offsets[i] = off;
        g_cursor[i] = off;
    }
    if (b == 0 && tid == 0) g_offsets[NN] = s_total;
}

// ---------------- 4) fused GEMM(+attn) and CSR scatter ----------------
// blocks [0, G_GEMM): GEMM x = h_node @ W (fp32x2 FMA), attn epilogue, fp16 copy
// blocks [G_GEMM, ..): scatter edges (+ self loops) into CSR
__global__ void k_gemm_scatter(const float* __restrict__ A, const float* __restrict__ W,
                               const float* __restrict__ att_src,
                               const float* __restrict__ att_dst,
                               const int* __restrict__ ei) {
    __shared__ __align__(16) float As[128 * 66];

    if (blockIdx.x >= G_GEMM) {
        // -------- scatter branch --------
        int t = (blockIdx.x - G_GEMM) * blockDim.x + threadIdx.x;
        const int EQ = EE / 4;
        if (t < EQ) {
            int4 s = ((const int4*)ei)[t];
            int4 d = ((const int4*)(ei + EE))[t];
            int p;
            p = atomicAdd(&g_cursor[d.x], 1); g_ssrc[p] = s.x;
            p = atomicAdd(&g_cursor[d.y], 1); g_ssrc[p] = s.y;
            p = atomicAdd(&g_cursor[d.z], 1); g_ssrc[p] = s.z;
            p = atomicAdd(&g_cursor[d.w], 1); g_ssrc[p] = s.w;
        } else if (t - EQ < NN) {
            int n = t - EQ;
            int p = atomicAdd(&g_cursor[n], 1);
            g_ssrc[p] = n;
        }
        return;
    }

    // -------- GEMM branch --------
    int tid = threadIdx.x;
    int tc = tid & 31;         // col group (4 cols)
    int tr = tid >> 5;         // row group (8 rows) == warp id
    int row0 = blockIdx.x * 64;

    const float4* Ag = (const float4*)A;
    for (int i = tid; i < 64 * 32; i += 256) {
        int r = i >> 5, kq = i & 31;
        int row = row0 + r;
        float4 v = (row < NN) ? Ag[(size_t)row * 32 + kq] : make_float4(0.f, 0.f, 0.f, 0.f);
        As[(4 * kq + 0) * 66 + r] = v.x;
        As[(4 * kq + 1) * 66 + r] = v.y;
        As[(4 * kq + 2) * 66 + r] = v.z;
        As[(4 * kq + 3) * 66 + r] = v.w;
    }
    __syncthreads();

    unsigned long long acc[4][4];
    #pragma unroll
    for (int r = 0; r < 4; r++)
        #pragma unroll
        for (int c = 0; c < 4; c++) acc[r][c] = 0ull;

    const float4* Wg = (const float4*)W;
    int rbase = tr * 8;

    #pragma unroll 4
    for (int k = 0; k < 128; k++) {
        float4 w4 = __ldg(&Wg[k * 32 + tc]);
        unsigned long long ww[4];
        asm("mov.b64 %0, {%1, %1};" : "=l"(ww[0]) : "f"(w4.x));
        asm("mov.b64 %0, {%1, %1};" : "=l"(ww[1]) : "f"(w4.y));
        asm("mov.b64 %0, {%1, %1};" : "=l"(ww[2]) : "f"(w4.z));
        asm("mov.b64 %0, {%1, %1};" : "=l"(ww[3]) : "f"(w4.w));
        unsigned long long ap[4];
        #pragma unroll
        for (int r = 0; r < 4; r++) {
            float2 a2 = *(const float2*)&As[k * 66 + rbase + 2 * r];
            asm("mov.b64 %0, {%1, %2};" : "=l"(ap[r]) : "f"(a2.x), "f"(a2.y));
        }
        #pragma unroll
        for (int r = 0; r < 4; r++)
            #pragma unroll
            for (int c = 0; c < 4; c++)
                asm("fma.rn.f32x2 %0, %1, %2, %0;" : "+l"(acc[r][c]) : "l"(ap[r]), "l"(ww[c]));
    }

    float4 sA4 = ((const float4*)att_src)[tc];
    float4 dA4 = ((const float4*)att_dst)[tc];

    #pragma unroll
    for (int r = 0; r < 4; r++) {
        float lo[4], hi[4];
        #pragma unroll
        for (int c = 0; c < 4; c++)
            asm("mov.b64 {%0, %1}, %2;" : "=f"(lo[c]), "=f"(hi[c]) : "l"(acc[r][c]));
        int rowA = row0 + rbase + 2 * r;
        int rowB = rowA + 1;
        if (rowA < NN) {
            ((float4*)g_x)[(size_t)rowA * 32 + tc] = make_float4(lo[0], lo[1], lo[2], lo[3]);
            half2 h0 = __floats2half2_rn(lo[0], lo[1]);
            half2 h1 = __floats2half2_rn(lo[2], lo[3]);
            ((uint2*)g_xh)[(size_t)rowA * 32 + tc] =
                make_uint2(*(unsigned*)&h0, *(unsigned*)&h1);
        }
        if (rowB < NN) {
            ((float4*)g_x)[(size_t)rowB * 32 + tc] = make_float4(hi[0], hi[1], hi[2], hi[3]);
            half2 h0 = __floats2half2_rn(hi[0], hi[1]);
            half2 h1 = __floats2half2_rn(hi[2], hi[3]);
            ((uint2*)g_xh)[(size_t)rowB * 32 + tc] =
                make_uint2(*(unsigned*)&h0, *(unsigned*)&h1);
        }

        float psA = lo[0] * sA4.x + lo[1] * sA4.y + lo[2] * sA4.z + lo[3] * sA4.w;
        float pdA = lo[0] * dA4.x + lo[1] * dA4.y + lo[2] * dA4.z + lo[3] * dA4.w;
        float psB = hi[0] * sA4.x + hi[1] * sA4.y + hi[2] * sA4.z + hi[3] * sA4.w;
        float pdB = hi[0] * dA4.x + hi[1] * dA4.y + hi[2] * dA4.z + hi[3] * dA4.w;
        #pragma unroll
        for (int d = 8; d >= 1; d >>= 1) {
            psA += __shfl_xor_sync(0xffffffffu, psA, d);
            pdA += __shfl_xor_sync(0xffffffffu, pdA, d);
            psB += __shfl_xor_sync(0xffffffffu, psB, d);
            pdB += __shfl_xor_sync(0xffffffffu, pdB, d);
        }
        if ((tc == 0 || tc == 16)) {
            int hh = tc >> 4;
            if (rowA < NN) { g_as[2 * rowA + hh] = psA; g_ad[2 * rowA + hh] = pdA; }
            if (rowB < NN) { g_as[2 * rowB + hh] = psB; g_ad[2 * rowB + hh] = pdB; }
        }
    }
}

// ---------------- 5) single-pass edge softmax + aggregate (fp16 gather) ----
__device__ __forceinline__ float leaky(float x) {
    return x > 0.f ? x : NEG_SLOPE * x;
}

__global__ void k_aggregate(const float* __restrict__ bias, float* __restrict__ out) {
    int w = (blockIdx.x * blockDim.x + threadIdx.x) >> 5;
    if (w >= NN) return;
    int lane = threadIdx.x & 31;
    int h = lane >> 4;
    int beg = g_offsets[w], end = g_offsets[w + 1];

    float adh = g_ad[2 * w + h];
    const uint2* xh = (const uint2*)g_xh;

    float den = 0.f;
    float4 acc = make_float4(0.f, 0.f, 0.f, 0.f);

    for (int base = beg; base < end; base += 32) {
        int nb = min(32, end - base);
        int idx = 0;
        float2 as2 = make_float2(0.f, 0.f);
        if (lane < nb) {
            idx = g_ssrc[base + lane];
            as2 = *(const float2*)&g_as[2 * idx];
        }
        if (nb == 32) {
            #pragma unroll 8
            for (int jj = 0; jj < 32; jj++) {
                int s = __shfl_sync(0xffffffffu, idx, jj);
                float a0 = __shfl_sync(0xffffffffu, as2.x, jj);
                float a1 = __shfl_sync(0xffffffffu, as2.y, jj);
                float p = __expf(leaky((h ? a1 : a0) + adh));
                uint2 hv = xh[(size_t)s * 32 + lane];
                float2 f01 = __half22float2(*(half2*)&hv.x);
                float2 f23 = __half22float2(*(half2*)&hv.y);
                den += p;
                acc.x += p * f01.x;
                acc.y += p * f01.y;
                acc.z += p * f23.x;
                acc.w += p * f23.y;
            }
        } else {
            for (int jj = 0; jj < nb; jj++) {
                int s = __shfl_sync(0xffffffffu, idx, jj);
                float a0 = __shfl_sync(0xffffffffu, as2.x, jj);
                float a1 = __shfl_sync(0xffffffffu, as2.y, jj);
                float p = __expf(leaky((h ? a1 : a0) + adh));
                uint2 hv = xh[(size_t)s * 32 + lane];
                float2 f01 = __half22float2(*(half2*)&hv.x);
                float2 f23 = __half22float2(*(half2*)&hv.y);
                den += p;
                acc.x += p * f01.x;
                acc.y += p * f01.y;
                acc.z += p * f23.x;
                acc.w += p * f23.y;
            }
        }
    }

    float inv = 1.0f / den;
    float4 b = ((const float4*)bias)[lane];
    acc.x = acc.x * inv + b.x;
    acc.y = acc.y * inv + b.y;
    acc.z = acc.z * inv + b.z;
    acc.w = acc.w * inv + b.w;
    acc.x = acc.x > 0.f ? acc.x : expm1f(acc.x);
    acc.y = acc.y > 0.f ? acc.y : expm1f(acc.y);
    acc.z = acc.z > 0.f ? acc.z : expm1f(acc.z);
    acc.w = acc.w > 0.f ? acc.w : expm1f(acc.w);
    ((float4*)out)[(size_t)w * 32 + lane] = acc;
}

// ---------------- launch ----------------
extern "C" void kernel_launch(void* const* d_in, const int* in_sizes, int n_in,
                              void* d_out, int out_size) {
    const float* h_node  = (const float*)d_in[0];
    const int*   ei      = (const int*)d_in[1];
    const float* W       = (const float*)d_in[2];
    const float* att_src = (const float*)d_in[3];
    const float* att_dst = (const float*)d_in[4];
    const float* bias    = (const float*)d_in[5];
    float* out = (float*)d_out;

    k_init_counts<<<(NN / 4 + 255) / 256, 256>>>();
    k_hist<<<(EE / 4 + 255) / 256, 256>>>(ei);
    k_chunksum<<<NCHUNK, 256>>>();
    k_scan2<<<NCHUNK, 1024>>>();
    int scat_blocks = (EE / 4 + NN + 255) / 256;
    k_gemm_scatter<<<G_GEMM + scat_blocks, 256>>>(h_node, W, att_src, att_dst, ei);
    k_aggregate<<<(NN * 32 + 255) / 256, 256>>>(bias, out);
}